// round 2
// baseline (speedup 1.0000x reference)
#include <cuda_runtime.h>

// ShadingLayer: out[b,c,h,w] = sum_k L[b,c,k] * H_k(n[b,:,h,w])
// H_k are 2nd-order real SH basis funcs with fixed attenuation constants.
// Constants folded into L per-thread; per pixel: 8 basis terms + 27 FMA.
//
// d_in[0]: recnormalch fp32 (64,3,512,512)  -> nx plane, ny plane, nz plane per batch
// d_in[1]: fc_light    fp32 (64,27)
// d_out  : fp32 (64,3,512,512)

#define C1f 0.8862269254527580f   // pi       * sqrt(1/(4pi))
#define C2f 1.0233267079464885f   // (2pi/3)  * sqrt(3/(4pi))
#define C3f 0.2477079561003757f   // (pi/4)*0.5*sqrt(5/(4pi))
#define C4f 0.8580855308097834f   // (pi/4)*3 * sqrt(5/(12pi))
#define C5f 0.4290427654048917f   // (pi/4)*3 * sqrt(5/(48pi))

static __device__ __forceinline__ float4 ldg4(const float* p) {
    return __ldg(reinterpret_cast<const float4*>(p));
}

__global__ __launch_bounds__(256)
void shading_kernel(const float* __restrict__ nrm,
                    const float* __restrict__ light,
                    float* __restrict__ out) {
    constexpr int HW = 512 * 512;          // pixels per plane
    constexpr int V4_PER_BATCH = HW / 4;   // 65536 float4 groups per plane

    const unsigned g = blockIdx.x * 256u + threadIdx.x;   // global float4 group
    const int b = g >> 16;                 // / V4_PER_BATCH (pow2)
    const int v = g & (V4_PER_BATCH - 1);  // float4 index within plane

    // ---- load + fold light coefficients for this batch (L2 broadcast) ----
    const float* Lb = light + b * 27;
    float a[3][9];
    #pragma unroll
    for (int c = 0; c < 3; c++) {
        a[c][0] = C1f * __ldg(Lb + 9 * c + 0);
        a[c][1] = C2f * __ldg(Lb + 9 * c + 1);
        a[c][2] = C2f * __ldg(Lb + 9 * c + 2);
        a[c][3] = C2f * __ldg(Lb + 9 * c + 3);
        a[c][4] = C3f * __ldg(Lb + 9 * c + 4);
        a[c][5] = C4f * __ldg(Lb + 9 * c + 5);
        a[c][6] = C4f * __ldg(Lb + 9 * c + 6);
        a[c][7] = C5f * __ldg(Lb + 9 * c + 7);
        a[c][8] = C4f * __ldg(Lb + 9 * c + 8);
    }

    // ---- load 4 pixels of (nx, ny, nz) ----
    const float* base = nrm + (size_t)b * 3 * HW + (size_t)v * 4;
    float4 X = ldg4(base);
    float4 Y = ldg4(base + HW);
    float4 Z = ldg4(base + 2 * HW);

    float xs[4] = {X.x, X.y, X.z, X.w};
    float ys[4] = {Y.x, Y.y, Y.z, Y.w};
    float zs[4] = {Z.x, Z.y, Z.z, Z.w};
    float o[3][4];

    #pragma unroll
    for (int j = 0; j < 4; j++) {
        const float x = xs[j], y = ys[j], z = zs[j];
        const float xx = x * x;
        const float yy = y * y;
        const float b5 = 2.0f * z * z - xx - yy;   // 2z^2 - x^2 - y^2
        const float b6 = x * z;
        const float b7 = y * z;
        const float b8 = xx - yy;
        const float b9 = x * y;
        #pragma unroll
        for (int c = 0; c < 3; c++) {
            float r = a[c][0];
            r = fmaf(a[c][1], z,  r);
            r = fmaf(a[c][2], x,  r);
            r = fmaf(a[c][3], y,  r);
            r = fmaf(a[c][4], b5, r);
            r = fmaf(a[c][5], b6, r);
            r = fmaf(a[c][6], b7, r);
            r = fmaf(a[c][7], b8, r);
            r = fmaf(a[c][8], b9, r);
            o[c][j] = r;
        }
    }

    // ---- store 4 pixels of each output channel ----
    float* obase = out + (size_t)b * 3 * HW + (size_t)v * 4;
    #pragma unroll
    for (int c = 0; c < 3; c++) {
        float4 w = make_float4(o[c][0], o[c][1], o[c][2], o[c][3]);
        *reinterpret_cast<float4*>(obase + (size_t)c * HW) = w;
    }
}

extern "C" void kernel_launch(void* const* d_in, const int* in_sizes, int n_in,
                              void* d_out, int out_size) {
    const float* nrm   = (const float*)d_in[0];   // (64,3,512,512)
    const float* light = (const float*)d_in[1];   // (64,27)
    float* out = (float*)d_out;                   // (64,3,512,512)

    // 64 batches * 65536 float4-groups / 256 threads = 16384 blocks
    shading_kernel<<<16384, 256>>>(nrm, light, out);
}

// round 3
// speedup vs baseline: 1.0359x; 1.0359x over previous
#include <cuda_runtime.h>

// ShadingLayer: out[b,c,h,w] = sum_k L[b,c,k] * H_k(n[b,:,h,w])
// HBM-bound streaming kernel. R2: 2 float4-groups per thread with all 6
// LDG.128 front-batched (MLP 3 -> 6), streaming cache hints (ldcs/stcs).
//
// d_in[0]: recnormalch fp32 (64,3,512,512)
// d_in[1]: fc_light    fp32 (64,27)
// d_out  : fp32 (64,3,512,512)

#define C1f 0.8862269254527580f
#define C2f 1.0233267079464885f
#define C3f 0.2477079561003757f
#define C4f 0.8580855308097834f
#define C5f 0.4290427654048917f

static __device__ __forceinline__ float4 ldcs4(const float* p) {
    return __ldcs(reinterpret_cast<const float4*>(p));
}
static __device__ __forceinline__ void stcs4(float* p, float4 v) {
    __stcs(reinterpret_cast<float4*>(p), v);
}

__global__ __launch_bounds__(256)
void shading_kernel(const float* __restrict__ nrm,
                    const float* __restrict__ light,
                    float* __restrict__ out) {
    constexpr int HW = 512 * 512;        // pixels per plane
    // 65536 float4-groups per plane; 512 groups per block -> 128 blocks/batch
    const unsigned bid = blockIdx.x;
    const int b   = bid >> 7;            // batch
    const int blk = bid & 127;           // block within batch
    const int v0  = blk * 512 + threadIdx.x;   // first float4-group
    // second group = v0 + 256 (still coalesced across the block)

    const float* nb = nrm + (size_t)b * 3 * HW;

    // ---- front-batch all 6 data loads (MLP=6) ----
    const float* p0 = nb + (size_t)v0 * 4;
    const float* p1 = p0 + 1024;               // +256 groups * 4 floats
    float4 X0 = ldcs4(p0);
    float4 Y0 = ldcs4(p0 + HW);
    float4 Z0 = ldcs4(p0 + 2 * HW);
    float4 X1 = ldcs4(p1);
    float4 Y1 = ldcs4(p1 + HW);
    float4 Z1 = ldcs4(p1 + 2 * HW);

    // ---- fold light coefficients (L2-broadcast hits) ----
    const float* Lb = light + b * 27;
    float a[3][9];
    #pragma unroll
    for (int c = 0; c < 3; c++) {
        a[c][0] = C1f * __ldg(Lb + 9 * c + 0);
        a[c][1] = C2f * __ldg(Lb + 9 * c + 1);
        a[c][2] = C2f * __ldg(Lb + 9 * c + 2);
        a[c][3] = C2f * __ldg(Lb + 9 * c + 3);
        a[c][4] = C3f * __ldg(Lb + 9 * c + 4);
        a[c][5] = C4f * __ldg(Lb + 9 * c + 5);
        a[c][6] = C4f * __ldg(Lb + 9 * c + 6);
        a[c][7] = C5f * __ldg(Lb + 9 * c + 7);
        a[c][8] = C4f * __ldg(Lb + 9 * c + 8);
    }

    float* ob = out + (size_t)b * 3 * HW;

    #pragma unroll
    for (int g = 0; g < 2; g++) {
        const float4 X = g ? X1 : X0;
        const float4 Y = g ? Y1 : Y0;
        const float4 Z = g ? Z1 : Z0;
        const float xs[4] = {X.x, X.y, X.z, X.w};
        const float ys[4] = {Y.x, Y.y, Y.z, Y.w};
        const float zs[4] = {Z.x, Z.y, Z.z, Z.w};
        float o[3][4];

        #pragma unroll
        for (int j = 0; j < 4; j++) {
            const float x = xs[j], y = ys[j], z = zs[j];
            const float xx = x * x;
            const float yy = y * y;
            const float b5 = 2.0f * z * z - xx - yy;
            const float b6 = x * z;
            const float b7 = y * z;
            const float b8 = xx - yy;
            const float b9 = x * y;
            #pragma unroll
            for (int c = 0; c < 3; c++) {
                float r = a[c][0];
                r = fmaf(a[c][1], z,  r);
                r = fmaf(a[c][2], x,  r);
                r = fmaf(a[c][3], y,  r);
                r = fmaf(a[c][4], b5, r);
                r = fmaf(a[c][5], b6, r);
                r = fmaf(a[c][6], b7, r);
                r = fmaf(a[c][7], b8, r);
                r = fmaf(a[c][8], b9, r);
                o[c][j] = r;
            }
        }

        float* q = ob + (size_t)(g ? v0 + 256 : v0) * 4;
        #pragma unroll
        for (int c = 0; c < 3; c++) {
            stcs4(q + (size_t)c * HW,
                  make_float4(o[c][0], o[c][1], o[c][2], o[c][3]));
        }
    }
}

extern "C" void kernel_launch(void* const* d_in, const int* in_sizes, int n_in,
                              void* d_out, int out_size) {
    const float* nrm   = (const float*)d_in[0];
    const float* light = (const float*)d_in[1];
    float* out = (float*)d_out;

    // 64 batches * 128 blocks each = 8192 blocks, 256 threads,
    // 2 float4-groups per thread
    shading_kernel<<<8192, 256>>>(nrm, light, out);
}